// round 16
// baseline (speedup 1.0000x reference)
#include <cuda_runtime.h>
#include <cuda_bf16.h>

// LengthRegulator: out[b, t, :] = phoneme[b, tok(b,t), :]
// tok(b,t) = searchsorted_right(inclusive_cumsum(durations[b,:]), t), clip N-1.
// Shapes (fixed): B=16, N=256, D=512, T=2048. float32.
//
// FINAL. Converged at the hardware store-stream roofline: 67MB of output
// written once at ~4.86 TB/s sustained (invariant across STG.128/STG.256/
// __stcs/TMA-bulk/dual-path stores, occupancy 8.6-83%, and read-traffic
// reductions of ~70%). Geometry: 1024 blocks x 256 threads, 32 frames/block,
// warp-0 shuffle-scan preamble (1 barrier), register-reuse gather (reload
// only on warp-uniform token change), streaming coalesced stores.

#define LR_B 16
#define LR_N 256
#define LR_D 512
#define LR_T 2048
#define FPB 32
#define THREADS 256
#define VPF 128                       // float4 per 2KB frame
#define FPT 16                        // frames per thread (FPB/2)

__global__ __launch_bounds__(THREADS)
void length_regulator_kernel(const float4* __restrict__ phoneme4,
                             const int* __restrict__ durations,
                             float4* __restrict__ out4)
{
    const int b = blockIdx.y;
    const int frame_base = blockIdx.x * FPB;
    const int tid = threadIdx.x;

    __shared__ int s_ends[LR_N];
    __shared__ int s_tok[FPB];

    // Warp 0: shuffle scan (lane owns durations[8L..8L+7]) + binary search.
    if (tid < 32) {
        const int lane = tid;
        const int4* drow = (const int4*)(durations + b * LR_N);
        int4 a = drow[lane * 2 + 0];
        int4 c = drow[lane * 2 + 1];
        int e0 = a.x;
        int e1 = e0 + a.y;
        int e2 = e1 + a.z;
        int e3 = e2 + a.w;
        int e4 = e3 + c.x;
        int e5 = e4 + c.y;
        int e6 = e5 + c.z;
        int e7 = e6 + c.w;
        int x = e7;
        #pragma unroll
        for (int off = 1; off < 32; off <<= 1) {
            int y = __shfl_up_sync(0xffffffffu, x, off);
            if (lane >= off) x += y;
        }
        const int excl = x - e7;
        s_ends[lane * 8 + 0] = e0 + excl;
        s_ends[lane * 8 + 1] = e1 + excl;
        s_ends[lane * 8 + 2] = e2 + excl;
        s_ends[lane * 8 + 3] = e3 + excl;
        s_ends[lane * 8 + 4] = e4 + excl;
        s_ends[lane * 8 + 5] = e5 + excl;
        s_ends[lane * 8 + 6] = e6 + excl;
        s_ends[lane * 8 + 7] = e7 + excl;
        __syncwarp();

        // lower-bound: first n with ends[n] > t (9 steps for N=256)
        const int t = frame_base + lane;
        int lo = 0, hi = LR_N;
        #pragma unroll
        for (int it = 0; it < 9; ++it) {
            if (lo < hi) {
                int mid = (lo + hi) >> 1;
                if (s_ends[mid] > t) hi = mid; else lo = mid + 1;
            }
        }
        s_tok[lane] = (lo < LR_N) ? lo : (LR_N - 1);
    }
    __syncthreads();

    // Thread owns column (tid & 127) for frames [half*16, half*16+16).
    // All 32 lanes of a warp share the same frame set -> the token-change
    // branch is warp-uniform (no divergence); stores stay 512B-coalesced.
    const int col  = tid & (VPF - 1);
    const int half = tid >> 7;            // 0 or 1
    const int f0   = half * FPT;

    // preload this thread's 16 token indices (4 x LDS.128)
    int tk[FPT];
    #pragma unroll
    for (int q = 0; q < FPT / 4; ++q) {
        int4 v = ((const int4*)s_tok)[half * (FPT / 4) + q];
        tk[q * 4 + 0] = v.x;
        tk[q * 4 + 1] = v.y;
        tk[q * 4 + 2] = v.z;
        tk[q * 4 + 3] = v.w;
    }

    const float4* __restrict__ ph_col =
        phoneme4 + (size_t)b * LR_N * VPF + col;
    float4* __restrict__ out_col =
        out4 + ((size_t)b * LR_T + frame_base + f0) * VPF + col;

    float4 v = ph_col[(size_t)tk[0] * VPF];
    __stcs(&out_col[0], v);
    #pragma unroll
    for (int j = 1; j < FPT; ++j) {
        if (tk[j] != tk[j - 1])               // warp-uniform
            v = ph_col[(size_t)tk[j] * VPF];
        __stcs(&out_col[(size_t)j * VPF], v);
    }
}

extern "C" void kernel_launch(void* const* d_in, const int* in_sizes, int n_in,
                              void* d_out, int out_size)
{
    const float4* phoneme4  = (const float4*)d_in[0];   // (B, N, D) f32
    const int*    durations = (const int*)d_in[1];      // (B, N) i32
    float4*       out4      = (float4*)d_out;           // (B, T, D) f32

    dim3 grid(LR_T / FPB, LR_B);  // (64, 16) = 1024 blocks
    length_regulator_kernel<<<grid, THREADS>>>(phoneme4, durations, out4);
}